// round 1
// baseline (speedup 1.0000x reference)
#include <cuda_runtime.h>
#include <math.h>

#define N_NODES 2048
#define D_DIM   128
#define E_DIM   8
#define GITERS  8
#define K_BIG   (N_NODES * E_DIM)   /* 16384 */
#define NSPLIT  16
#define KCHUNK  (K_BIG / NSPLIT)    /* 1024 */

/* ---------------- scratch layout (floats) ---------------- */
#define OFF_H0    0L
#define OFF_H1    262144L
#define OFF_PEDGE 524288L                 /* [16384][128] = 2097152 */
#define OFF_PART  2621440L                /* [16][2048][128] = 4194304 */
#define OFF_MSG   6815744L                /* [2048][128] */
#define OFF_GI    7077888L                /* [2048][384] */
#define OFF_GH    7864320L                /* [2048][384] */
#define OFF_HA    8650752L                /* [2048][128] */
#define SCRATCH_FLOATS 8912896L           /* ~35.7 MB */

__device__ float g_scratch[SCRATCH_FLOATS];

/* ---------------- generic NN GEMM: C = A@B (+bias), 64x64 tile ----------- */
__global__ void gemm_nn(const float* __restrict__ A, const float* __restrict__ B,
                        const float* __restrict__ bias, float* __restrict__ C,
                        int M, int Nn, int K, int lda, int ldb, int ldc,
                        long aBatch, long bBatch, long cBatch)
{
    __shared__ float As[16][65];
    __shared__ float Bs[16][68];
    A += (long)blockIdx.z * aBatch;
    B += (long)blockIdx.z * bBatch;
    C += (long)blockIdx.z * cBatch;
    const int m0 = blockIdx.y * 64, n0 = blockIdx.x * 64;
    const int tid = threadIdx.x;
    const int tr = tid >> 4, tc = tid & 15;
    float acc[4][4] = {};

    for (int k0 = 0; k0 < K; k0 += 16) {
        {   /* A tile 64x16 -> transposed As[k][m] */
            int ar = tid >> 2;
            int ac = (tid & 3) << 2;
            float4 v = *(const float4*)&A[(long)(m0 + ar) * lda + k0 + ac];
            As[ac + 0][ar] = v.x; As[ac + 1][ar] = v.y;
            As[ac + 2][ar] = v.z; As[ac + 3][ar] = v.w;
        }
        {   /* B tile 16x64 */
            int br = tid >> 4;
            int bc = (tid & 15) << 2;
            *(float4*)&Bs[br][bc] = *(const float4*)&B[(long)(k0 + br) * ldb + n0 + bc];
        }
        __syncthreads();
#pragma unroll
        for (int kk = 0; kk < 16; kk++) {
            float a0 = As[kk][tr * 4 + 0];
            float a1 = As[kk][tr * 4 + 1];
            float a2 = As[kk][tr * 4 + 2];
            float a3 = As[kk][tr * 4 + 3];
            float4 bv = *(const float4*)&Bs[kk][tc * 4];
            acc[0][0] += a0 * bv.x; acc[0][1] += a0 * bv.y; acc[0][2] += a0 * bv.z; acc[0][3] += a0 * bv.w;
            acc[1][0] += a1 * bv.x; acc[1][1] += a1 * bv.y; acc[1][2] += a1 * bv.z; acc[1][3] += a1 * bv.w;
            acc[2][0] += a2 * bv.x; acc[2][1] += a2 * bv.y; acc[2][2] += a2 * bv.z; acc[2][3] += a2 * bv.w;
            acc[3][0] += a3 * bv.x; acc[3][1] += a3 * bv.y; acc[3][2] += a3 * bv.z; acc[3][3] += a3 * bv.w;
        }
        __syncthreads();
    }
#pragma unroll
    for (int u = 0; u < 4; u++) {
        int row = m0 + tr * 4 + u;
#pragma unroll
        for (int v = 0; v < 4; v++) {
            int col = n0 + tc * 4 + v;
            float x = acc[u][v];
            if (bias) x += bias[col];
            C[(long)row * ldc + col] = x;
        }
    }
}

/* ------------- big message GEMM, split-K into partial buffer -------------
 * part[split][t][d] = sum_{k in chunk} edge_flat[k][t] * per_edge_flat[k][d]
 * edge_flat[k=(s*8+e)][t] lives at edge[s*16384 + t*8 + e]  (coalesced in t,e)
 */
__global__ void msg_gemm(const float* __restrict__ edge)
{
    const float* __restrict__ P = g_scratch + OFF_PEDGE;
    float* __restrict__ part = g_scratch + OFF_PART;

    const int split = blockIdx.x;
    const int t0 = blockIdx.y * 64;
    const int tid = threadIdx.x;

    __shared__ float As[32][65];     /* [kk][t_local] */
    __shared__ float Ps[32][128];    /* [kk][d]       */

    const int tq = tid >> 4;   /* 0..15: owns t rows {tq, tq+16, tq+32, tq+48} */
    const int dg = tid & 15;   /* d group: cols dg*8 .. dg*8+7 */

    float acc[4][8] = {};
    const int kbase = split * KCHUNK;

    for (int k0 = kbase; k0 < kbase + KCHUNK; k0 += 32) {
        const int sbase = k0 >> 3;   /* 4 s values per step */
#pragma unroll
        for (int r = 0; r < 2; r++) {        /* A tile: 2048 floats */
            int lin = tid + r * 256;          /* 0..511 */
            int s_l = lin >> 7;               /* 0..3   */
            int f4  = lin & 127;              /* 0..127 */
            float4 v = *(const float4*)&edge[(long)(sbase + s_l) * K_BIG + t0 * 8 + f4 * 4];
            int tl = f4 >> 1;                 /* t local 0..63 */
            int kk = s_l * 8 + ((f4 & 1) << 2);
            As[kk + 0][tl] = v.x; As[kk + 1][tl] = v.y;
            As[kk + 2][tl] = v.z; As[kk + 3][tl] = v.w;
        }
#pragma unroll
        for (int r = 0; r < 4; r++) {        /* P tile: 4096 floats */
            int lin = tid + r * 256;          /* 0..1023 */
            int row = lin >> 5;
            int c4  = (lin & 31) << 2;
            *(float4*)&Ps[row][c4] = *(const float4*)&P[(long)(k0 + row) * 128 + c4];
        }
        __syncthreads();
#pragma unroll
        for (int kk = 0; kk < 32; kk++) {
            float a[4];
#pragma unroll
            for (int u = 0; u < 4; u++) a[u] = As[kk][tq + 16 * u];
            float4 p0 = *(const float4*)&Ps[kk][dg * 8];
            float4 p1 = *(const float4*)&Ps[kk][dg * 8 + 4];
            float b[8] = {p0.x, p0.y, p0.z, p0.w, p1.x, p1.y, p1.z, p1.w};
#pragma unroll
            for (int u = 0; u < 4; u++)
#pragma unroll
                for (int v = 0; v < 8; v++) acc[u][v] += a[u] * b[v];
        }
        __syncthreads();
    }
#pragma unroll
    for (int u = 0; u < 4; u++) {
        int t = t0 + tq + 16 * u;
        float* dst = part + ((long)split * N_NODES + t) * 128 + dg * 8;
        float4 w0 = make_float4(acc[u][0], acc[u][1], acc[u][2], acc[u][3]);
        float4 w1 = make_float4(acc[u][4], acc[u][5], acc[u][6], acc[u][7]);
        *(float4*)&dst[0] = w0;
        *(float4*)&dst[4] = w1;
    }
}

/* ---------------- reduce split-K partials + bias ---------------- */
__global__ void reduce_bias(const float* __restrict__ bias)
{
    int idx = blockIdx.x * 256 + threadIdx.x;   /* < 262144 */
    const float* __restrict__ part = g_scratch + OFF_PART;
    float s = bias[idx & 127];
#pragma unroll
    for (int p = 0; p < NSPLIT; p++) s += part[(long)p * 262144 + idx];
    g_scratch[OFF_MSG + idx] = s;
}

/* ---------------- GRU elementwise update ---------------- */
__global__ void gru_kernel(int cur)
{
    int idx = blockIdx.x * 256 + threadIdx.x;   /* < 262144 */
    int i = idx >> 7, d = idx & 127;
    const float* __restrict__ gi = g_scratch + OFF_GI;
    const float* __restrict__ gh = g_scratch + OFF_GH;
    const float* __restrict__ h  = g_scratch + (cur ? OFF_H1 : OFF_H0);
    float* __restrict__ ho = g_scratch + (cur ? OFF_H0 : OFF_H1);

    long base = (long)i * 384 + d;
    float ir = gi[base], iz = gi[base + 128], inn = gi[base + 256];
    float hr = gh[base], hz = gh[base + 128], hn  = gh[base + 256];
    float hv = h[idx];
    float r = 1.f / (1.f + expf(-(ir + hr)));
    float z = 1.f / (1.f + expf(-(iz + hz)));
    float n = tanhf(inn + r * hn);
    ho[idx] = (1.f - z) * n + z * hv;
}

/* ---------------- NT GEMM for logits: C[i][j] = sum_k A[i][k]*B[j][k] ----- */
__global__ void gemm_nt(const float* __restrict__ A, const float* __restrict__ B,
                        float* __restrict__ C, int Nn, int K)
{
    __shared__ float As[32][66];
    __shared__ float Bs[32][66];
    const int i0 = blockIdx.y * 64, j0 = blockIdx.x * 64;
    const int tid = threadIdx.x;
    const int tr = tid >> 4, tc = tid & 15;
    float acc[4][4] = {};

    for (int k0 = 0; k0 < K; k0 += 32) {
#pragma unroll
        for (int r = 0; r < 2; r++) {
            int lin = tid + r * 256;
            int row = lin >> 3;
            int c4  = (lin & 7) << 2;
            float4 v = *(const float4*)&A[(long)(i0 + row) * K + k0 + c4];
            As[c4 + 0][row] = v.x; As[c4 + 1][row] = v.y;
            As[c4 + 2][row] = v.z; As[c4 + 3][row] = v.w;
        }
#pragma unroll
        for (int r = 0; r < 2; r++) {
            int lin = tid + r * 256;
            int row = lin >> 3;
            int c4  = (lin & 7) << 2;
            float4 v = *(const float4*)&B[(long)(j0 + row) * K + k0 + c4];
            Bs[c4 + 0][row] = v.x; Bs[c4 + 1][row] = v.y;
            Bs[c4 + 2][row] = v.z; Bs[c4 + 3][row] = v.w;
        }
        __syncthreads();
#pragma unroll
        for (int kk = 0; kk < 32; kk++) {
            float a[4], b[4];
#pragma unroll
            for (int u = 0; u < 4; u++) a[u] = As[kk][tr + 16 * u];
#pragma unroll
            for (int v = 0; v < 4; v++) b[v] = Bs[kk][tc + 16 * v];
#pragma unroll
            for (int u = 0; u < 4; u++)
#pragma unroll
                for (int v = 0; v < 4; v++) acc[u][v] += a[u] * b[v];
        }
        __syncthreads();
    }
#pragma unroll
    for (int u = 0; u < 4; u++)
#pragma unroll
        for (int v = 0; v < 4; v++)
            C[(long)(i0 + tr + 16 * u) * Nn + (j0 + tc + 16 * v)] = acc[u][v];
}

/* ---------------- launcher ---------------- */
extern "C" void kernel_launch(void* const* d_in, const int* in_sizes, int n_in,
                              void* d_out, int out_size)
{
    const float* node = (const float*)d_in[0];   /* [2048][128]      */
    const float* edge = (const float*)d_in[1];   /* [2048][2048][8]  */
    const float* Wmsg = (const float*)d_in[2];   /* [8][128][128]    */
    const float* bmsg = (const float*)d_in[3];   /* [128]            */
    const float* Wi   = (const float*)d_in[4];   /* [128][384]       */
    const float* Wh   = (const float*)d_in[5];   /* [128][384]       */
    const float* bgru = (const float*)d_in[6];   /* [384]            */
    const float* Aro  = (const float*)d_in[7];   /* [128][128]       */
    float* out = (float*)d_out;                  /* [2048][2048]     */

    float* scratch = nullptr;
    cudaGetSymbolAddress((void**)&scratch, g_scratch);
    float* H0  = scratch + OFF_H0;
    float* H1  = scratch + OFF_H1;
    float* PE  = scratch + OFF_PEDGE;
    float* MSG = scratch + OFF_MSG;
    float* GI  = scratch + OFF_GI;
    float* GH  = scratch + OFF_GH;
    float* HA  = scratch + OFF_HA;

    cudaMemcpyAsync(H0, node, (size_t)N_NODES * D_DIM * sizeof(float),
                    cudaMemcpyDeviceToDevice);

    int cur = 0;
    for (int it = 0; it < GITERS; it++) {
        float* Hc = cur ? H1 : H0;
        /* per_edge[s][e][:] = h[s] @ Wmsg[e]  (batched over e) */
        gemm_nn<<<dim3(2, 32, 8), 256>>>(Hc, Wmsg, nullptr, PE,
                                         N_NODES, 128, 128, 128, 128, E_DIM * D_DIM,
                                         0, (long)D_DIM * D_DIM, (long)D_DIM);
        /* big GEMM, split-K partials */
        msg_gemm<<<dim3(NSPLIT, 32), 256>>>(edge);
        reduce_bias<<<1024, 256>>>(bmsg);
        /* gi = msg@Wi + b_gru ; gh = h@Wh */
        gemm_nn<<<dim3(6, 32, 1), 256>>>(MSG, Wi, bgru, GI,
                                         N_NODES, 384, 128, 128, 384, 384, 0, 0, 0);
        gemm_nn<<<dim3(6, 32, 1), 256>>>(Hc, Wh, nullptr, GH,
                                         N_NODES, 384, 128, 128, 384, 384, 0, 0, 0);
        gru_kernel<<<1024, 256>>>(cur);
        cur ^= 1;
    }
    float* Hf = cur ? H1 : H0;
    /* readout: hA = h@A ; logits = hA @ h^T */
    gemm_nn<<<dim3(2, 32, 1), 256>>>(Hf, Aro, nullptr, HA,
                                     N_NODES, 128, 128, 128, 128, 128, 0, 0, 0);
    gemm_nt<<<dim3(32, 32), 256>>>(HA, Hf, out, N_NODES, 128);
}

// round 3
// speedup vs baseline: 3.1120x; 3.1120x over previous
#include <cuda_runtime.h>
#include <cuda_bf16.h>
#include <math.h>
#include <stdint.h>

#define N_NODES 2048
#define D_DIM   128
#define E_DIM   8
#define GITERS  8
#define K_BIG   (N_NODES * E_DIM)   /* 16384 */

/* ---------------- scratch layout (floats) ---------------- */
#define OFF_H0    0L
#define OFF_H1    262144L
#define OFF_PEDGE 524288L                 /* [2048][8][128] */
#define OFF_MSG   2621440L                /* [2048][128] */
#define OFF_GI    2883584L                /* [2048][384] */
#define OFF_GH    3670016L                /* [2048][384] */
#define OFF_HA    4456448L                /* [2048][128] */
#define SCRATCH_FLOATS 4718592L

__device__ float g_scratch[SCRATCH_FLOATS];

/* bf16 split operands for the big tensor-core GEMM */
__device__ __align__(16) __nv_bfloat16 g_edgeK_hi[(long)N_NODES * K_BIG];  /* [t][e*2048+s] */
__device__ __align__(16) __nv_bfloat16 g_edgeK_lo[(long)N_NODES * K_BIG];
__device__ __align__(16) __nv_bfloat16 g_Pt_hi[(long)D_DIM * K_BIG];       /* [d][e*2048+s] */
__device__ __align__(16) __nv_bfloat16 g_Pt_lo[(long)D_DIM * K_BIG];
__device__ float g_part[8L * N_NODES * D_DIM];                             /* [e][t][d] */

/* ================= helpers ================= */
__device__ __forceinline__ uint32_t smem_u32(const void* p) {
    uint32_t a;
    asm("{ .reg .u64 t; cvta.to.shared.u64 t, %1; cvt.u32.u64 %0, t; }" : "=r"(a) : "l"(p));
    return a;
}
__device__ __forceinline__ void ldsm_x4(uint32_t addr, uint32_t& r0, uint32_t& r1,
                                        uint32_t& r2, uint32_t& r3) {
    asm volatile("ldmatrix.sync.aligned.m8n8.x4.shared.b16 {%0,%1,%2,%3}, [%4];"
                 : "=r"(r0), "=r"(r1), "=r"(r2), "=r"(r3) : "r"(addr));
}
__device__ __forceinline__ void ldsm_x2(uint32_t addr, uint32_t& r0, uint32_t& r1) {
    asm volatile("ldmatrix.sync.aligned.m8n8.x2.shared.b16 {%0,%1}, [%2];"
                 : "=r"(r0), "=r"(r1) : "r"(addr));
}
__device__ __forceinline__ void mma_bf16(float* c, const uint32_t* a, const uint32_t* b) {
    asm volatile("mma.sync.aligned.m16n8k16.row.col.f32.bf16.bf16.f32 "
                 "{%0,%1,%2,%3}, {%4,%5,%6,%7}, {%8,%9}, {%0,%1,%2,%3};"
                 : "+f"(c[0]), "+f"(c[1]), "+f"(c[2]), "+f"(c[3])
                 : "r"(a[0]), "r"(a[1]), "r"(a[2]), "r"(a[3]), "r"(b[0]), "r"(b[1]));
}
__device__ __forceinline__ void cp_async16(uint32_t saddr, const void* gaddr) {
    asm volatile("cp.async.cg.shared.global [%0], [%1], 16;" :: "r"(saddr), "l"(gaddr) : "memory");
}
#define CP_COMMIT() asm volatile("cp.async.commit_group;" ::: "memory")
#define CP_WAIT2()  asm volatile("cp.async.wait_group 2;" ::: "memory")

/* =============== one-time edge transpose+split =============== */
__global__ void edge_split_kernel(const float* __restrict__ edge)
{
    __shared__ float sm[64][132];
    const int s0 = blockIdx.x * 64, t0 = blockIdx.y * 16;
    const int tid = threadIdx.x;
#pragma unroll
    for (int it = 0; it < 8; it++) {
        int lin = it * 256 + tid;
        int s_l = lin >> 5, f4 = lin & 31;
        float4 v = *(const float4*)&edge[(long)(s0 + s_l) * K_BIG + t0 * 8 + f4 * 4];
        *(float4*)&sm[s_l][f4 * 4] = v;
    }
    __syncthreads();
    const int pair = tid >> 1, half = tid & 1;
    const int t_l = pair >> 3, e = pair & 7;
    const long obase = (long)(t0 + t_l) * K_BIG + (long)e * 2048 + s0 + half * 32;
#pragma unroll
    for (int q = 0; q < 4; q++) {
        __align__(16) __nv_bfloat16 hb[8];
        __align__(16) __nv_bfloat16 lb[8];
#pragma unroll
        for (int j = 0; j < 8; j++) {
            float f = sm[half * 32 + q * 8 + j][t_l * 8 + e];
            __nv_bfloat16 h = __float2bfloat16(f);
            hb[j] = h;
            lb[j] = __float2bfloat16(f - __bfloat162float(h));
        }
        *(uint4*)&g_edgeK_hi[obase + q * 8] = *(const uint4*)hb;
        *(uint4*)&g_edgeK_lo[obase + q * 8] = *(const uint4*)lb;
    }
}

/* =============== per-iter Pt transpose+split =============== */
__global__ void pt_split_kernel()
{
    __shared__ float sm[64][132];
    const float* __restrict__ PE = g_scratch + OFF_PEDGE;
    const int s0 = blockIdx.x * 64, e = blockIdx.y;
    const int tid = threadIdx.x;
#pragma unroll
    for (int it = 0; it < 8; it++) {
        int lin = it * 256 + tid;
        int s_l = lin >> 5, f4 = lin & 31;
        float4 v = *(const float4*)&PE[(long)(s0 + s_l) * 1024 + e * 128 + f4 * 4];
        *(float4*)&sm[s_l][f4 * 4] = v;
    }
    __syncthreads();
    const int d = tid >> 1, half = tid & 1;
    const long obase = (long)d * K_BIG + (long)e * 2048 + s0 + half * 32;
#pragma unroll
    for (int q = 0; q < 4; q++) {
        __align__(16) __nv_bfloat16 hb[8];
        __align__(16) __nv_bfloat16 lb[8];
#pragma unroll
        for (int j = 0; j < 8; j++) {
            float f = sm[half * 32 + q * 8 + j][d];
            __nv_bfloat16 h = __float2bfloat16(f);
            hb[j] = h;
            lb[j] = __float2bfloat16(f - __bfloat162float(h));
        }
        *(uint4*)&g_Pt_hi[obase + q * 8] = *(const uint4*)hb;
        *(uint4*)&g_Pt_lo[obase + q * 8] = *(const uint4*)lb;
    }
}

/* =============== big GEMM via mma.sync (HMMA bf16) ===============
 * grid (16 t-tiles, 8 e).  part[e][t0+0..127][0..127] =
 *   sum_s edgeK[t][e*2048+s] * Pt[d][e*2048+s]
 * 3-product bf16 split: AhBh + AlBh + AhBl (fp32 accum).
 * SMEM stage: Ah|Al|Bh|Bl tiles, each 128 rows x 64 bf16 (swizzled), 64KB.
 * 3-stage cp.async ring. */
#define STAGE_BYTES 65536
#define TILE_B      16384

__global__ void __launch_bounds__(256, 1) msg_mma_kernel()
{
    extern __shared__ char smem[];
    const uint32_t sb = smem_u32(smem);
    const int tid = threadIdx.x;
    const int wid = tid >> 5, lane = tid & 31;
    const int warpM = wid >> 2, warpN = wid & 3;       /* 2 x 4 warp grid */
    const int t0 = blockIdx.x * 128;
    const int e = blockIdx.y;
    const long koff = (long)e * 2048;

    const __nv_bfloat16* __restrict__ bAh = g_edgeK_hi + (long)t0 * K_BIG + koff;
    const __nv_bfloat16* __restrict__ bAl = g_edgeK_lo + (long)t0 * K_BIG + koff;
    const __nv_bfloat16* __restrict__ bBh = g_Pt_hi + koff;
    const __nv_bfloat16* __restrict__ bBl = g_Pt_lo + koff;

    float acc[4][4][4] = {};   /* [mt][nt][frag] */

    /* issue one chunk's loads into stage `st` */
    auto issue = [&](int chunk, int st) {
        const int kofs = chunk * 64;
        const __nv_bfloat16* srcs[4] = { bAh + kofs, bAl + kofs, bBh + kofs, bBl + kofs };
        const uint32_t stage = sb + st * STAGE_BYTES;
#pragma unroll
        for (int j = 0; j < 4; j++) {
#pragma unroll
            for (int it = 0; it < 4; it++) {
                int seg = it * 256 + tid;
                int row = seg >> 3, c = seg & 7;
                uint32_t saddr = stage + j * TILE_B + row * 128 + ((c ^ (row & 7)) << 4);
                cp_async16(saddr, srcs[j] + (long)row * K_BIG + c * 8);
            }
        }
    };

    issue(0, 0); CP_COMMIT();
    issue(1, 1); CP_COMMIT();
    issue(2, 2); CP_COMMIT();

    for (int chunk = 0; chunk < 32; chunk++) {
        CP_WAIT2();
        __syncthreads();
        const uint32_t stage = sb + (chunk % 3) * STAGE_BYTES;

#pragma unroll
        for (int ks = 0; ks < 4; ks++) {
            uint32_t Ah[4][4], Al[4][4], Bh[4][2], Bl[4][2];
            /* A fragments: rows = warpM*64 + mt*16 + (lane&15), colblock = ks*2 + (lane>>4) */
            const int ra_l = lane & 15, ca = ks * 2 + (lane >> 4);
#pragma unroll
            for (int mt = 0; mt < 4; mt++) {
                int row = warpM * 64 + mt * 16 + ra_l;
                uint32_t off = row * 128 + ((ca ^ (row & 7)) << 4);
                ldsm_x4(stage + off,            Ah[mt][0], Ah[mt][1], Ah[mt][2], Ah[mt][3]);
                ldsm_x4(stage + TILE_B + off,   Al[mt][0], Al[mt][1], Al[mt][2], Al[mt][3]);
            }
            /* B fragments: rows = warpN*32 + nt*8 + (lane&7), colblock = ks*2 + ((lane>>3)&1) */
            const int rb_l = lane & 7, cb = ks * 2 + ((lane >> 3) & 1);
#pragma unroll
            for (int nt = 0; nt < 4; nt++) {
                int row = warpN * 32 + nt * 8 + rb_l;
                uint32_t off = row * 128 + ((cb ^ (row & 7)) << 4);
                ldsm_x2(stage + 2 * TILE_B + off, Bh[nt][0], Bh[nt][1]);
                ldsm_x2(stage + 3 * TILE_B + off, Bl[nt][0], Bl[nt][1]);
            }
#pragma unroll
            for (int mt = 0; mt < 4; mt++)
#pragma unroll
                for (int nt = 0; nt < 4; nt++) {
                    mma_bf16(acc[mt][nt], Ah[mt], Bh[nt]);
                    mma_bf16(acc[mt][nt], Al[mt], Bh[nt]);
                    mma_bf16(acc[mt][nt], Ah[mt], Bl[nt]);
                }
        }
        __syncthreads();
        if (chunk + 3 < 32) issue(chunk + 3, chunk % 3);
        CP_COMMIT();
    }

    /* epilogue: write fp32 partials */
    const int gr = lane >> 2, idx = lane & 3;
    float* dstE = g_part + (long)e * N_NODES * D_DIM;
#pragma unroll
    for (int mt = 0; mt < 4; mt++) {
        int r0 = t0 + warpM * 64 + mt * 16 + gr;
#pragma unroll
        for (int nt = 0; nt < 4; nt++) {
            int col = warpN * 32 + nt * 8 + 2 * idx;
            *(float2*)&dstE[(long)r0 * D_DIM + col]       = make_float2(acc[mt][nt][0], acc[mt][nt][1]);
            *(float2*)&dstE[(long)(r0 + 8) * D_DIM + col] = make_float2(acc[mt][nt][2], acc[mt][nt][3]);
        }
    }
}

/* ---------------- generic NN GEMM ---------------- */
__global__ void gemm_nn(const float* __restrict__ A, const float* __restrict__ B,
                        const float* __restrict__ bias, float* __restrict__ C,
                        int M, int Nn, int K, int lda, int ldb, int ldc,
                        long aBatch, long bBatch, long cBatch)
{
    __shared__ float As[16][65];
    __shared__ float Bs[16][68];
    A += (long)blockIdx.z * aBatch;
    B += (long)blockIdx.z * bBatch;
    C += (long)blockIdx.z * cBatch;
    const int m0 = blockIdx.y * 64, n0 = blockIdx.x * 64;
    const int tid = threadIdx.x;
    const int tr = tid >> 4, tc = tid & 15;
    float acc[4][4] = {};

    for (int k0 = 0; k0 < K; k0 += 16) {
        {
            int ar = tid >> 2;
            int ac = (tid & 3) << 2;
            float4 v = *(const float4*)&A[(long)(m0 + ar) * lda + k0 + ac];
            As[ac + 0][ar] = v.x; As[ac + 1][ar] = v.y;
            As[ac + 2][ar] = v.z; As[ac + 3][ar] = v.w;
        }
        {
            int br = tid >> 4;
            int bc = (tid & 15) << 2;
            *(float4*)&Bs[br][bc] = *(const float4*)&B[(long)(k0 + br) * ldb + n0 + bc];
        }
        __syncthreads();
#pragma unroll
        for (int kk = 0; kk < 16; kk++) {
            float a0 = As[kk][tr * 4 + 0];
            float a1 = As[kk][tr * 4 + 1];
            float a2 = As[kk][tr * 4 + 2];
            float a3 = As[kk][tr * 4 + 3];
            float4 bv = *(const float4*)&Bs[kk][tc * 4];
            acc[0][0] += a0 * bv.x; acc[0][1] += a0 * bv.y; acc[0][2] += a0 * bv.z; acc[0][3] += a0 * bv.w;
            acc[1][0] += a1 * bv.x; acc[1][1] += a1 * bv.y; acc[1][2] += a1 * bv.z; acc[1][3] += a1 * bv.w;
            acc[2][0] += a2 * bv.x; acc[2][1] += a2 * bv.y; acc[2][2] += a2 * bv.z; acc[2][3] += a2 * bv.w;
            acc[3][0] += a3 * bv.x; acc[3][1] += a3 * bv.y; acc[3][2] += a3 * bv.z; acc[3][3] += a3 * bv.w;
        }
        __syncthreads();
    }
#pragma unroll
    for (int u = 0; u < 4; u++) {
        int row = m0 + tr * 4 + u;
#pragma unroll
        for (int v = 0; v < 4; v++) {
            int col = n0 + tc * 4 + v;
            float x = acc[u][v];
            if (bias) x += bias[col];
            C[(long)row * ldc + col] = x;
        }
    }
}

/* ---------------- reduce 8 split-K partials + bias ---------------- */
__global__ void reduce_bias(const float* __restrict__ bias)
{
    int idx = blockIdx.x * 256 + threadIdx.x;
    float s = bias[idx & 127];
#pragma unroll
    for (int p = 0; p < 8; p++) s += g_part[(long)p * 262144 + idx];
    g_scratch[OFF_MSG + idx] = s;
}

/* ---------------- GRU elementwise update ---------------- */
__global__ void gru_kernel(int cur)
{
    int idx = blockIdx.x * 256 + threadIdx.x;
    int i = idx >> 7, d = idx & 127;
    const float* __restrict__ gi = g_scratch + OFF_GI;
    const float* __restrict__ gh = g_scratch + OFF_GH;
    const float* __restrict__ h  = g_scratch + (cur ? OFF_H1 : OFF_H0);
    float* __restrict__ ho = g_scratch + (cur ? OFF_H0 : OFF_H1);

    long base = (long)i * 384 + d;
    float ir = gi[base], iz = gi[base + 128], inn = gi[base + 256];
    float hr = gh[base], hz = gh[base + 128], hn  = gh[base + 256];
    float hv = h[idx];
    float r = 1.f / (1.f + expf(-(ir + hr)));
    float z = 1.f / (1.f + expf(-(iz + hz)));
    float n = tanhf(inn + r * hn);
    ho[idx] = (1.f - z) * n + z * hv;
}

/* ---------------- NT GEMM for logits ---------------- */
__global__ void gemm_nt(const float* __restrict__ A, const float* __restrict__ B,
                        float* __restrict__ C, int Nn, int K)
{
    __shared__ float As[32][66];
    __shared__ float Bs[32][66];
    const int i0 = blockIdx.y * 64, j0 = blockIdx.x * 64;
    const int tid = threadIdx.x;
    const int tr = tid >> 4, tc = tid & 15;
    float acc[4][4] = {};

    for (int k0 = 0; k0 < K; k0 += 32) {
#pragma unroll
        for (int r = 0; r < 2; r++) {
            int lin = tid + r * 256;
            int row = lin >> 3;
            int c4  = (lin & 7) << 2;
            float4 v = *(const float4*)&A[(long)(i0 + row) * K + k0 + c4];
            As[c4 + 0][row] = v.x; As[c4 + 1][row] = v.y;
            As[c4 + 2][row] = v.z; As[c4 + 3][row] = v.w;
        }
#pragma unroll
        for (int r = 0; r < 2; r++) {
            int lin = tid + r * 256;
            int row = lin >> 3;
            int c4  = (lin & 7) << 2;
            float4 v = *(const float4*)&B[(long)(j0 + row) * K + k0 + c4];
            Bs[c4 + 0][row] = v.x; Bs[c4 + 1][row] = v.y;
            Bs[c4 + 2][row] = v.z; Bs[c4 + 3][row] = v.w;
        }
        __syncthreads();
#pragma unroll
        for (int kk = 0; kk < 32; kk++) {
            float a[4], b[4];
#pragma unroll
            for (int u = 0; u < 4; u++) a[u] = As[kk][tr + 16 * u];
#pragma unroll
            for (int v = 0; v < 4; v++) b[v] = Bs[kk][tc + 16 * v];
#pragma unroll
            for (int u = 0; u < 4; u++)
#pragma unroll
                for (int v = 0; v < 4; v++) acc[u][v] += a[u] * b[v];
        }
        __syncthreads();
    }
#pragma unroll
    for (int u = 0; u < 4; u++)
#pragma unroll
        for (int v = 0; v < 4; v++)
            C[(long)(i0 + tr + 16 * u) * Nn + (j0 + tc + 16 * v)] = acc[u][v];
}

/* ---------------- launcher ---------------- */
extern "C" void kernel_launch(void* const* d_in, const int* in_sizes, int n_in,
                              void* d_out, int out_size)
{
    const float* node = (const float*)d_in[0];
    const float* edge = (const float*)d_in[1];
    const float* Wmsg = (const float*)d_in[2];
    const float* bmsg = (const float*)d_in[3];
    const float* Wi   = (const float*)d_in[4];
    const float* Wh   = (const float*)d_in[5];
    const float* bgru = (const float*)d_in[6];
    const float* Aro  = (const float*)d_in[7];
    float* out = (float*)d_out;

    float* scratch = nullptr;
    cudaGetSymbolAddress((void**)&scratch, g_scratch);
    float* H0  = scratch + OFF_H0;
    float* H1  = scratch + OFF_H1;
    float* PE  = scratch + OFF_PEDGE;
    float* MSG = scratch + OFF_MSG;
    float* GI  = scratch + OFF_GI;
    float* GH  = scratch + OFF_GH;
    float* HA  = scratch + OFF_HA;

    cudaFuncSetAttribute(msg_mma_kernel, cudaFuncAttributeMaxDynamicSharedMemorySize,
                         3 * STAGE_BYTES);

    cudaMemcpyAsync(H0, node, (size_t)N_NODES * D_DIM * sizeof(float),
                    cudaMemcpyDeviceToDevice);

    /* one-time: transpose + bf16-split the (constant) edge tensor */
    edge_split_kernel<<<dim3(32, 128), 256>>>(edge);

    int cur = 0;
    for (int it = 0; it < GITERS; it++) {
        float* Hc = cur ? H1 : H0;
        gemm_nn<<<dim3(2, 32, 8), 256>>>(Hc, Wmsg, nullptr, PE,
                                         N_NODES, 128, 128, 128, 128, E_DIM * D_DIM,
                                         0, (long)D_DIM * D_DIM, (long)D_DIM);
        pt_split_kernel<<<dim3(32, 8), 256>>>();
        msg_mma_kernel<<<dim3(16, 8), 256, 3 * STAGE_BYTES>>>();
        reduce_bias<<<1024, 256>>>(bmsg);
        gemm_nn<<<dim3(6, 32, 1), 256>>>(MSG, Wi, bgru, GI,
                                         N_NODES, 384, 128, 128, 384, 384, 0, 0, 0);
        gemm_nn<<<dim3(6, 32, 1), 256>>>(Hc, Wh, nullptr, GH,
                                         N_NODES, 384, 128, 128, 384, 384, 0, 0, 0);
        gru_kernel<<<1024, 256>>>(cur);
        cur ^= 1;
    }
    float* Hf = cur ? H1 : H0;
    gemm_nn<<<dim3(2, 32, 1), 256>>>(Hf, Aro, nullptr, HA,
                                     N_NODES, 128, 128, 128, 128, 128, 0, 0, 0);
    gemm_nt<<<dim3(32, 32), 256>>>(HA, Hf, out, N_NODES, 128);
}

// round 4
// speedup vs baseline: 3.7423x; 1.2025x over previous
#include <cuda_runtime.h>
#include <cuda_bf16.h>
#include <math.h>
#include <stdint.h>

#define N_NODES 2048
#define D_DIM   128
#define E_DIM   8
#define GITERS  8
#define K_BIG   (N_NODES * E_DIM)   /* 16384 */

/* ---------------- scratch layout (floats) ---------------- */
#define OFF_H0    0L
#define OFF_H1    262144L
#define OFF_MSG   524288L
#define OFF_GI    786432L                 /* [2048][384] */
#define OFF_GH    1572864L
#define OFF_HA    2359296L
#define SCRATCH_FLOATS 2621440L

__device__ float g_scratch[SCRATCH_FLOATS];

__device__ __align__(16) __nv_bfloat16 g_edgeK_hi[(long)N_NODES * K_BIG];  /* [t][e*2048+s] */
__device__ __align__(16) __nv_bfloat16 g_edgeK_lo[(long)N_NODES * K_BIG];
__device__ __align__(16) __nv_bfloat16 g_Pt_hi[(long)D_DIM * K_BIG];       /* [d][e*2048+s] */
__device__ __align__(16) __nv_bfloat16 g_Pt_lo[(long)D_DIM * K_BIG];
__device__ float g_part[16L * N_NODES * D_DIM];                            /* [p][t][d] */

/* ================= helpers ================= */
__device__ __forceinline__ uint32_t smem_u32(const void* p) {
    uint32_t a;
    asm("{ .reg .u64 t; cvta.to.shared.u64 t, %1; cvt.u32.u64 %0, t; }" : "=r"(a) : "l"(p));
    return a;
}
__device__ __forceinline__ void ldsm_x4(uint32_t addr, uint32_t& r0, uint32_t& r1,
                                        uint32_t& r2, uint32_t& r3) {
    asm volatile("ldmatrix.sync.aligned.m8n8.x4.shared.b16 {%0,%1,%2,%3}, [%4];"
                 : "=r"(r0), "=r"(r1), "=r"(r2), "=r"(r3) : "r"(addr));
}
__device__ __forceinline__ void ldsm_x2(uint32_t addr, uint32_t& r0, uint32_t& r1) {
    asm volatile("ldmatrix.sync.aligned.m8n8.x2.shared.b16 {%0,%1}, [%2];"
                 : "=r"(r0), "=r"(r1) : "r"(addr));
}
__device__ __forceinline__ void mma_bf16(float* c, const uint32_t* a, const uint32_t* b) {
    asm volatile("mma.sync.aligned.m16n8k16.row.col.f32.bf16.bf16.f32 "
                 "{%0,%1,%2,%3}, {%4,%5,%6,%7}, {%8,%9}, {%0,%1,%2,%3};"
                 : "+f"(c[0]), "+f"(c[1]), "+f"(c[2]), "+f"(c[3])
                 : "r"(a[0]), "r"(a[1]), "r"(a[2]), "r"(a[3]), "r"(b[0]), "r"(b[1]));
}
__device__ __forceinline__ void cp_async16(uint32_t saddr, const void* gaddr) {
    asm volatile("cp.async.cg.shared.global [%0], [%1], 16;" :: "r"(saddr), "l"(gaddr) : "memory");
}
#define CP_COMMIT() asm volatile("cp.async.commit_group;" ::: "memory")
#define CP_WAIT2()  asm volatile("cp.async.wait_group 2;" ::: "memory")

__device__ __forceinline__ void split4(float4 v, __nv_bfloat16* hb, __nv_bfloat16* lb) {
    float f[4] = { v.x, v.y, v.z, v.w };
#pragma unroll
    for (int j = 0; j < 4; j++) {
        __nv_bfloat16 h = __float2bfloat16(f[j]);
        hb[j] = h;
        lb[j] = __float2bfloat16(f[j] - __bfloat162float(h));
    }
}

/* fill split smem tile [128 rows][128 k] (256B rows, xor-swizzled) from
 * row-major fp32 source with contiguous k (row stride ldg floats) */
__device__ __forceinline__ void load_split_rowk(char* smc, uint32_t hioff, uint32_t looff,
        const float* __restrict__ g, int ldg, int tid)
{
#pragma unroll
    for (int i = 0; i < 16; i++) {
        int lin = i * 256 + tid;
        int row = lin >> 5, c4 = lin & 31;
        float4 v = *(const float4*)&g[(long)row * ldg + c4 * 4];
        __align__(8) __nv_bfloat16 hb[4], lb[4];
        split4(v, hb, lb);
        uint32_t off = row * 256 + (((c4 >> 1) ^ (row & 7)) << 4) + ((c4 & 1) << 3);
        *(uint2*)(smc + hioff + off) = *(const uint2*)hb;
        *(uint2*)(smc + looff + off) = *(const uint2*)lb;
    }
}

/* fill split smem tile Bs[n][k] from B[k][n0+n] fp32 (row stride ldg) */
__device__ __forceinline__ void load_split_coln(char* smc, uint32_t hioff, uint32_t looff,
        const float* __restrict__ g /* = B + n0 */, int ldg, int tid)
{
    const int n = tid & 127;
#pragma unroll
    for (int i = 0; i < 16; i++) {
        int kg = i * 2 + (tid >> 7);          /* group of 4 consecutive k */
        float4 v;
        v.x = g[(long)(kg * 4 + 0) * ldg + n];
        v.y = g[(long)(kg * 4 + 1) * ldg + n];
        v.z = g[(long)(kg * 4 + 2) * ldg + n];
        v.w = g[(long)(kg * 4 + 3) * ldg + n];
        __align__(8) __nv_bfloat16 hb[4], lb[4];
        split4(v, hb, lb);
        uint32_t off = n * 256 + (((kg >> 1) ^ (n & 7)) << 4) + ((kg & 1) << 3);
        *(uint2*)(smc + hioff + off) = *(const uint2*)hb;
        *(uint2*)(smc + looff + off) = *(const uint2*)lb;
    }
}

/* K=128 one-shot mma core: acc += 3-product split GEMM on smem tiles */
__device__ __forceinline__ void mma_k128(uint32_t sb, uint32_t ah, uint32_t al,
        uint32_t bh, uint32_t bl, float acc[4][4][4], int warpM, int warpN, int lane)
{
#pragma unroll
    for (int ks = 0; ks < 8; ks++) {
        uint32_t Bh[4][2], Bl[4][2];
        const int cb = ks * 2 + ((lane >> 3) & 1);
#pragma unroll
        for (int nt = 0; nt < 4; nt++) {
            int row = warpN * 32 + nt * 8 + (lane & 7);
            uint32_t off = row * 256 + ((cb ^ (row & 7)) << 4);
            ldsm_x2(sb + bh + off, Bh[nt][0], Bh[nt][1]);
            ldsm_x2(sb + bl + off, Bl[nt][0], Bl[nt][1]);
        }
        const int ca = ks * 2 + (lane >> 4);
#pragma unroll
        for (int mt = 0; mt < 4; mt++) {
            int row = warpM * 64 + mt * 16 + (lane & 15);
            uint32_t off = row * 256 + ((ca ^ (row & 7)) << 4);
            uint32_t Ah[4], Al[4];
            ldsm_x4(sb + ah + off, Ah[0], Ah[1], Ah[2], Ah[3]);
            ldsm_x4(sb + al + off, Al[0], Al[1], Al[2], Al[3]);
#pragma unroll
            for (int nt = 0; nt < 4; nt++) {
                mma_bf16(acc[mt][nt], Ah, Bh[nt]);
                mma_bf16(acc[mt][nt], Al, Bh[nt]);
                mma_bf16(acc[mt][nt], Ah, Bl[nt]);
            }
        }
    }
}

#define T32K 32768u

/* ---------------- generic C = A@B (+bias) via HMMA, K=128 ---------------- */
__global__ void __launch_bounds__(256) lin_mma(const float* __restrict__ A,
        const float* __restrict__ B, const float* __restrict__ bias,
        float* __restrict__ C, int N)
{
    extern __shared__ char smc[];
    const uint32_t sb = smem_u32(smc);
    const int tid = threadIdx.x, wid = tid >> 5, lane = tid & 31;
    const int warpM = wid >> 2, warpN = wid & 3;
    const int m0 = blockIdx.x * 128, n0 = blockIdx.y * 128;

    load_split_rowk(smc, 0, T32K, A + (long)m0 * 128, 128, tid);
    load_split_coln(smc, 2 * T32K, 3 * T32K, B + n0, N, tid);
    __syncthreads();

    float acc[4][4][4] = {};
    mma_k128(sb, 0, T32K, 2 * T32K, 3 * T32K, acc, warpM, warpN, lane);

    const int gr = lane >> 2, idx = lane & 3;
#pragma unroll
    for (int mt = 0; mt < 4; mt++) {
        int r0 = m0 + warpM * 64 + mt * 16 + gr;
#pragma unroll
        for (int nt = 0; nt < 4; nt++) {
            int col = n0 + warpN * 32 + nt * 8 + 2 * idx;
            float b0 = bias ? bias[col] : 0.f;
            float b1 = bias ? bias[col + 1] : 0.f;
            *(float2*)&C[(long)r0 * N + col] =
                make_float2(acc[mt][nt][0] + b0, acc[mt][nt][1] + b1);
            *(float2*)&C[(long)(r0 + 8) * N + col] =
                make_float2(acc[mt][nt][2] + b0, acc[mt][nt][3] + b1);
        }
    }
}

/* ---------------- per-edge transform, transposed-split output ----------------
 * Pt[d][e*2048+s] = split( sum_k h[s,k] Wmsg[e,k,d] ).  grid (16 s-tiles, 8 e) */
__global__ void __launch_bounds__(256) pe_mma(const float* __restrict__ h,
                                              const float* __restrict__ Wmsg)
{
    extern __shared__ char smc[];
    const uint32_t sb = smem_u32(smc);
    const int tid = threadIdx.x, wid = tid >> 5, lane = tid & 31;
    const int warpM = wid >> 2, warpN = wid & 3;
    const int s0 = blockIdx.x * 128, e = blockIdx.y;

    load_split_rowk(smc, 0, T32K, h + (long)s0 * 128, 128, tid);
    load_split_coln(smc, 2 * T32K, 3 * T32K, Wmsg + (long)e * 16384, 128, tid);
    __syncthreads();

    float acc[4][4][4] = {};
    mma_k128(sb, 0, T32K, 2 * T32K, 3 * T32K, acc, warpM, warpN, lane);

    __syncthreads();
    float* tb = (float*)smc;                      /* [128 d][132] */
    const int gr = lane >> 2, idx = lane & 3;
#pragma unroll
    for (int mt = 0; mt < 4; mt++) {
        int sr = warpM * 64 + mt * 16 + gr;
#pragma unroll
        for (int nt = 0; nt < 4; nt++) {
            int d = warpN * 32 + nt * 8 + 2 * idx;
            tb[d * 132 + sr]           = acc[mt][nt][0];
            tb[(d + 1) * 132 + sr]     = acc[mt][nt][1];
            tb[d * 132 + sr + 8]       = acc[mt][nt][2];
            tb[(d + 1) * 132 + sr + 8] = acc[mt][nt][3];
        }
    }
    __syncthreads();
#pragma unroll
    for (int i = 0; i < 16; i++) {
        int lin = i * 256 + tid;
        int d = lin >> 5, c4 = lin & 31;
        int s = c4 * 4;
        float4 v = *(const float4*)&tb[d * 132 + s];
        __align__(8) __nv_bfloat16 hb[4], lb[4];
        split4(v, hb, lb);
        long o = (long)d * K_BIG + (long)e * 2048 + s0 + s;
        *(uint2*)&g_Pt_hi[o] = *(const uint2*)hb;
        *(uint2*)&g_Pt_lo[o] = *(const uint2*)lb;
    }
}

/* ---------------- readout NT: out[i][j] = sum_k hA[i,k] h[j,k] ---------------- */
__global__ void __launch_bounds__(256) nt_mma(const float* __restrict__ hA,
        const float* __restrict__ h, float* __restrict__ C)
{
    extern __shared__ char smc[];
    const uint32_t sb = smem_u32(smc);
    const int tid = threadIdx.x, wid = tid >> 5, lane = tid & 31;
    const int warpM = wid >> 2, warpN = wid & 3;
    const int i0 = blockIdx.x * 128, j0 = blockIdx.y * 128;

    load_split_rowk(smc, 0, T32K, hA + (long)i0 * 128, 128, tid);
    load_split_rowk(smc, 2 * T32K, 3 * T32K, h + (long)j0 * 128, 128, tid);
    __syncthreads();

    float acc[4][4][4] = {};
    mma_k128(sb, 0, T32K, 2 * T32K, 3 * T32K, acc, warpM, warpN, lane);

    const int gr = lane >> 2, idx = lane & 3;
#pragma unroll
    for (int mt = 0; mt < 4; mt++) {
        int r0 = i0 + warpM * 64 + mt * 16 + gr;
#pragma unroll
        for (int nt = 0; nt < 4; nt++) {
            int col = j0 + warpN * 32 + nt * 8 + 2 * idx;
            *(float2*)&C[(long)r0 * N_NODES + col] = make_float2(acc[mt][nt][0], acc[mt][nt][1]);
            *(float2*)&C[(long)(r0 + 8) * N_NODES + col] = make_float2(acc[mt][nt][2], acc[mt][nt][3]);
        }
    }
}

/* =============== one-time edge transpose+split =============== */
__global__ void edge_split_kernel(const float* __restrict__ edge)
{
    __shared__ float sm[64][132];
    const int s0 = blockIdx.x * 64, t0 = blockIdx.y * 16;
    const int tid = threadIdx.x;
#pragma unroll
    for (int it = 0; it < 8; it++) {
        int lin = it * 256 + tid;
        int s_l = lin >> 5, f4 = lin & 31;
        float4 v = *(const float4*)&edge[(long)(s0 + s_l) * K_BIG + t0 * 8 + f4 * 4];
        *(float4*)&sm[s_l][f4 * 4] = v;
    }
    __syncthreads();
    const int pair = tid >> 1, half = tid & 1;
    const int t_l = pair >> 3, e = pair & 7;
    const long obase = (long)(t0 + t_l) * K_BIG + (long)e * 2048 + s0 + half * 32;
#pragma unroll
    for (int q = 0; q < 4; q++) {
        __align__(16) __nv_bfloat16 hb[8];
        __align__(16) __nv_bfloat16 lb[8];
#pragma unroll
        for (int j = 0; j < 8; j++) {
            float f = sm[half * 32 + q * 8 + j][t_l * 8 + e];
            __nv_bfloat16 h = __float2bfloat16(f);
            hb[j] = h;
            lb[j] = __float2bfloat16(f - __bfloat162float(h));
        }
        *(uint4*)&g_edgeK_hi[obase + q * 8] = *(const uint4*)hb;
        *(uint4*)&g_edgeK_lo[obase + q * 8] = *(const uint4*)lb;
    }
}

/* =============== big message GEMM (pipelined HMMA) ===============
 * grid (16 t-tiles, 8 e, 2 s-halves); kchunk=32, 3-stage cp.async. */
#define MTILE_B 8192u
#define MSTAGE_B 32768u

__global__ void __launch_bounds__(256, 2) msg_mma_kernel()
{
    extern __shared__ char smc[];
    const uint32_t sb = smem_u32(smc);
    const int tid = threadIdx.x;
    const int wid = tid >> 5, lane = tid & 31;
    const int warpM = wid >> 2, warpN = wid & 3;
    const int t0 = blockIdx.x * 128;
    const int e = blockIdx.y, sh = blockIdx.z;
    const long koff = (long)e * 2048 + sh * 1024;

    const __nv_bfloat16* __restrict__ bAh = g_edgeK_hi + (long)t0 * K_BIG + koff;
    const __nv_bfloat16* __restrict__ bAl = g_edgeK_lo + (long)t0 * K_BIG + koff;
    const __nv_bfloat16* __restrict__ bBh = g_Pt_hi + koff;
    const __nv_bfloat16* __restrict__ bBl = g_Pt_lo + koff;

    float acc[4][4][4] = {};

    auto issue = [&](int chunk, int st) {
        const int kofs = chunk * 32;
        const __nv_bfloat16* srcs[4] = { bAh + kofs, bAl + kofs, bBh + kofs, bBl + kofs };
        const uint32_t stage = sb + st * MSTAGE_B;
#pragma unroll
        for (int j = 0; j < 4; j++) {
#pragma unroll
            for (int it = 0; it < 2; it++) {
                int seg = it * 256 + tid;       /* 0..511 */
                int row = seg >> 2, c = seg & 3;
                uint32_t saddr = stage + j * MTILE_B + row * 64 +
                                 ((c ^ ((row >> 1) & 3)) << 4);
                cp_async16(saddr, srcs[j] + (long)row * K_BIG + c * 8);
            }
        }
    };

    issue(0, 0); CP_COMMIT();
    issue(1, 1); CP_COMMIT();
    issue(2, 2); CP_COMMIT();

    for (int chunk = 0; chunk < 32; chunk++) {
        CP_WAIT2();
        __syncthreads();
        const uint32_t stage = sb + (chunk % 3) * MSTAGE_B;

#pragma unroll
        for (int ks = 0; ks < 2; ks++) {
            uint32_t Bh[4][2], Bl[4][2];
            const int cb = ks * 2 + ((lane >> 3) & 1);
#pragma unroll
            for (int nt = 0; nt < 4; nt++) {
                int row = warpN * 32 + nt * 8 + (lane & 7);
                uint32_t off = row * 64 + ((cb ^ ((row >> 1) & 3)) << 4);
                ldsm_x2(stage + 2 * MTILE_B + off, Bh[nt][0], Bh[nt][1]);
                ldsm_x2(stage + 3 * MTILE_B + off, Bl[nt][0], Bl[nt][1]);
            }
            const int ca = ks * 2 + (lane >> 4);
#pragma unroll
            for (int mt = 0; mt < 4; mt++) {
                int row = warpM * 64 + mt * 16 + (lane & 15);
                uint32_t off = row * 64 + ((ca ^ ((row >> 1) & 3)) << 4);
                uint32_t Ah[4], Al[4];
                ldsm_x4(stage + off, Ah[0], Ah[1], Ah[2], Ah[3]);
                ldsm_x4(stage + MTILE_B + off, Al[0], Al[1], Al[2], Al[3]);
#pragma unroll
                for (int nt = 0; nt < 4; nt++) {
                    mma_bf16(acc[mt][nt], Ah, Bh[nt]);
                    mma_bf16(acc[mt][nt], Al, Bh[nt]);
                    mma_bf16(acc[mt][nt], Ah, Bl[nt]);
                }
            }
        }
        __syncthreads();
        if (chunk + 3 < 32) issue(chunk + 3, chunk % 3);
        CP_COMMIT();
    }

    const int gr = lane >> 2, idx = lane & 3;
    float* dstE = g_part + (long)(e + 8 * sh) * N_NODES * D_DIM;
#pragma unroll
    for (int mt = 0; mt < 4; mt++) {
        int r0 = t0 + warpM * 64 + mt * 16 + gr;
#pragma unroll
        for (int nt = 0; nt < 4; nt++) {
            int col = warpN * 32 + nt * 8 + 2 * idx;
            *(float2*)&dstE[(long)r0 * D_DIM + col]       = make_float2(acc[mt][nt][0], acc[mt][nt][1]);
            *(float2*)&dstE[(long)(r0 + 8) * D_DIM + col] = make_float2(acc[mt][nt][2], acc[mt][nt][3]);
        }
    }
}

/* ---------------- reduce 16 split-K partials + bias ---------------- */
__global__ void reduce_bias(const float* __restrict__ bias)
{
    int idx = blockIdx.x * 256 + threadIdx.x;
    float s = bias[idx & 127];
#pragma unroll
    for (int p = 0; p < 16; p++) s += g_part[(long)p * 262144 + idx];
    g_scratch[OFF_MSG + idx] = s;
}

/* ---------------- GRU elementwise update ---------------- */
__global__ void gru_kernel(int cur)
{
    int idx = blockIdx.x * 256 + threadIdx.x;
    int i = idx >> 7, d = idx & 127;
    const float* __restrict__ gi = g_scratch + OFF_GI;
    const float* __restrict__ gh = g_scratch + OFF_GH;
    const float* __restrict__ h  = g_scratch + (cur ? OFF_H1 : OFF_H0);
    float* __restrict__ ho = g_scratch + (cur ? OFF_H0 : OFF_H1);

    long base = (long)i * 384 + d;
    float ir = gi[base], iz = gi[base + 128], inn = gi[base + 256];
    float hr = gh[base], hz = gh[base + 128], hn  = gh[base + 256];
    float hv = h[idx];
    float r = 1.f / (1.f + expf(-(ir + hr)));
    float z = 1.f / (1.f + expf(-(iz + hz)));
    float n = tanhf(inn + r * hn);
    ho[idx] = (1.f - z) * n + z * hv;
}

/* ---------------- launcher ---------------- */
extern "C" void kernel_launch(void* const* d_in, const int* in_sizes, int n_in,
                              void* d_out, int out_size)
{
    const float* node = (const float*)d_in[0];
    const float* edge = (const float*)d_in[1];
    const float* Wmsg = (const float*)d_in[2];
    const float* bmsg = (const float*)d_in[3];
    const float* Wi   = (const float*)d_in[4];
    const float* Wh   = (const float*)d_in[5];
    const float* bgru = (const float*)d_in[6];
    const float* Aro  = (const float*)d_in[7];
    float* out = (float*)d_out;

    float* scratch = nullptr;
    cudaGetSymbolAddress((void**)&scratch, g_scratch);
    float* H0  = scratch + OFF_H0;
    float* H1  = scratch + OFF_H1;
    float* MSG = scratch + OFF_MSG;
    float* GI  = scratch + OFF_GI;
    float* GH  = scratch + OFF_GH;
    float* HA  = scratch + OFF_HA;

    cudaFuncSetAttribute(msg_mma_kernel, cudaFuncAttributeMaxDynamicSharedMemorySize, 3 * MSTAGE_B);
    cudaFuncSetAttribute(lin_mma, cudaFuncAttributeMaxDynamicSharedMemorySize, 131072);
    cudaFuncSetAttribute(pe_mma, cudaFuncAttributeMaxDynamicSharedMemorySize, 131072);
    cudaFuncSetAttribute(nt_mma, cudaFuncAttributeMaxDynamicSharedMemorySize, 131072);

    cudaMemcpyAsync(H0, node, (size_t)N_NODES * D_DIM * sizeof(float),
                    cudaMemcpyDeviceToDevice);

    edge_split_kernel<<<dim3(32, 128), 256>>>(edge);

    int cur = 0;
    for (int it = 0; it < GITERS; it++) {
        float* Hc = cur ? H1 : H0;
        pe_mma<<<dim3(16, 8), 256, 131072>>>(Hc, Wmsg);
        msg_mma_kernel<<<dim3(16, 8, 2), 256, 3 * MSTAGE_B>>>();
        reduce_bias<<<1024, 256>>>(bmsg);
        lin_mma<<<dim3(16, 3), 256, 131072>>>(MSG, Wi, bgru, GI, 384);
        lin_mma<<<dim3(16, 3), 256, 131072>>>(Hc, Wh, nullptr, GH, 384);
        gru_kernel<<<1024, 256>>>(cur);
        cur ^= 1;
    }
    float* Hf = cur ? H1 : H0;
    lin_mma<<<dim3(16, 1), 256, 131072>>>(Hf, Aro, nullptr, HA, 128);
    nt_mma<<<dim3(16, 16), 256, 131072>>>(HA, Hf, out);
}

// round 5
// speedup vs baseline: 3.9711x; 1.0611x over previous
#include <cuda_runtime.h>
#include <cuda_bf16.h>
#include <math.h>
#include <stdint.h>

#define N_NODES 2048
#define D_DIM   128
#define E_DIM   8
#define GITERS  8
#define K_BIG   (N_NODES * E_DIM)   /* 16384 */

/* ---------------- scratch layout (floats) ---------------- */
#define OFF_H0    0L
#define OFF_H1    262144L
#define OFF_MSG   524288L
#define OFF_GI    786432L                 /* [2048][384] */
#define OFF_GH    1572864L
#define OFF_HA    2359296L
#define SCRATCH_FLOATS 2621440L

__device__ float g_scratch[SCRATCH_FLOATS];

__device__ __align__(16) __nv_bfloat16 g_edgeK_hi[(long)N_NODES * K_BIG];  /* [t][e*2048+s] */
__device__ __align__(16) __nv_bfloat16 g_edgeK_lo[(long)N_NODES * K_BIG];
__device__ __align__(16) __nv_bfloat16 g_Pt_hi[(long)D_DIM * K_BIG];       /* [d][e*2048+s] */
__device__ __align__(16) __nv_bfloat16 g_Pt_lo[(long)D_DIM * K_BIG];
__device__ __align__(16) __nv_bfloat16 g_part_hi[16L * N_NODES * D_DIM];   /* [p][t][d] */
__device__ __align__(16) __nv_bfloat16 g_part_lo[16L * N_NODES * D_DIM];

/* ================= helpers ================= */
__device__ __forceinline__ uint32_t smem_u32(const void* p) {
    uint32_t a;
    asm("{ .reg .u64 t; cvta.to.shared.u64 t, %1; cvt.u32.u64 %0, t; }" : "=r"(a) : "l"(p));
    return a;
}
__device__ __forceinline__ void ldsm_x4(uint32_t addr, uint32_t& r0, uint32_t& r1,
                                        uint32_t& r2, uint32_t& r3) {
    asm volatile("ldmatrix.sync.aligned.m8n8.x4.shared.b16 {%0,%1,%2,%3}, [%4];"
                 : "=r"(r0), "=r"(r1), "=r"(r2), "=r"(r3) : "r"(addr));
}
__device__ __forceinline__ void ldsm_x2(uint32_t addr, uint32_t& r0, uint32_t& r1) {
    asm volatile("ldmatrix.sync.aligned.m8n8.x2.shared.b16 {%0,%1}, [%2];"
                 : "=r"(r0), "=r"(r1) : "r"(addr));
}
__device__ __forceinline__ void mma_bf16(float* c, const uint32_t* a, const uint32_t* b) {
    asm volatile("mma.sync.aligned.m16n8k16.row.col.f32.bf16.bf16.f32 "
                 "{%0,%1,%2,%3}, {%4,%5,%6,%7}, {%8,%9}, {%0,%1,%2,%3};"
                 : "+f"(c[0]), "+f"(c[1]), "+f"(c[2]), "+f"(c[3])
                 : "r"(a[0]), "r"(a[1]), "r"(a[2]), "r"(a[3]), "r"(b[0]), "r"(b[1]));
}
__device__ __forceinline__ void cp_async16(uint32_t saddr, const void* gaddr) {
    asm volatile("cp.async.cg.shared.global [%0], [%1], 16;" :: "r"(saddr), "l"(gaddr) : "memory");
}
#define CP_COMMIT() asm volatile("cp.async.commit_group;" ::: "memory")
#define CP_WAIT2()  asm volatile("cp.async.wait_group 2;" ::: "memory")

__device__ __forceinline__ void split4(float4 v, __nv_bfloat16* hb, __nv_bfloat16* lb) {
    float f[4] = { v.x, v.y, v.z, v.w };
#pragma unroll
    for (int j = 0; j < 4; j++) {
        __nv_bfloat16 h = __float2bfloat16(f[j]);
        hb[j] = h;
        lb[j] = __float2bfloat16(f[j] - __bfloat162float(h));
    }
}
__device__ __forceinline__ void store_split2(__nv_bfloat16* hp, __nv_bfloat16* lp,
                                             long off, float x, float y) {
    __nv_bfloat16 hx = __float2bfloat16(x), hy = __float2bfloat16(y);
    __nv_bfloat16 lx = __float2bfloat16(x - __bfloat162float(hx));
    __nv_bfloat16 ly = __float2bfloat16(y - __bfloat162float(hy));
    __nv_bfloat162 hv; hv.x = hx; hv.y = hy;
    __nv_bfloat162 lv; lv.x = lx; lv.y = ly;
    *(__nv_bfloat162*)(hp + off) = hv;
    *(__nv_bfloat162*)(lp + off) = lv;
}

/* fill split smem tile [128 rows][128 k] (256B rows, xor-swizzled) */
__device__ __forceinline__ void load_split_rowk(char* smc, uint32_t hioff, uint32_t looff,
        const float* __restrict__ g, int ldg, int tid)
{
#pragma unroll
    for (int i = 0; i < 16; i++) {
        int lin = i * 256 + tid;
        int row = lin >> 5, c4 = lin & 31;
        float4 v = *(const float4*)&g[(long)row * ldg + c4 * 4];
        __align__(8) __nv_bfloat16 hb[4], lb[4];
        split4(v, hb, lb);
        uint32_t off = row * 256 + (((c4 >> 1) ^ (row & 7)) << 4) + ((c4 & 1) << 3);
        *(uint2*)(smc + hioff + off) = *(const uint2*)hb;
        *(uint2*)(smc + looff + off) = *(const uint2*)lb;
    }
}

/* fill split smem tile Bs[n][k] from B[k][n0+n] fp32 */
__device__ __forceinline__ void load_split_coln(char* smc, uint32_t hioff, uint32_t looff,
        const float* __restrict__ g, int ldg, int tid)
{
    const int n = tid & 127;
#pragma unroll
    for (int i = 0; i < 16; i++) {
        int kg = i * 2 + (tid >> 7);
        float4 v;
        v.x = g[(long)(kg * 4 + 0) * ldg + n];
        v.y = g[(long)(kg * 4 + 1) * ldg + n];
        v.z = g[(long)(kg * 4 + 2) * ldg + n];
        v.w = g[(long)(kg * 4 + 3) * ldg + n];
        __align__(8) __nv_bfloat16 hb[4], lb[4];
        split4(v, hb, lb);
        uint32_t off = n * 256 + (((kg >> 1) ^ (n & 7)) << 4) + ((kg & 1) << 3);
        *(uint2*)(smc + hioff + off) = *(const uint2*)hb;
        *(uint2*)(smc + looff + off) = *(const uint2*)lb;
    }
}

/* K=128 one-shot mma core */
__device__ __forceinline__ void mma_k128(uint32_t sb, uint32_t ah, uint32_t al,
        uint32_t bh, uint32_t bl, float acc[4][4][4], int warpM, int warpN, int lane)
{
#pragma unroll
    for (int ks = 0; ks < 8; ks++) {
        uint32_t Bh[4][2], Bl[4][2];
        const int cb = ks * 2 + ((lane >> 3) & 1);
#pragma unroll
        for (int nt = 0; nt < 4; nt++) {
            int row = warpN * 32 + nt * 8 + (lane & 7);
            uint32_t off = row * 256 + ((cb ^ (row & 7)) << 4);
            ldsm_x2(sb + bh + off, Bh[nt][0], Bh[nt][1]);
            ldsm_x2(sb + bl + off, Bl[nt][0], Bl[nt][1]);
        }
        const int ca = ks * 2 + (lane >> 4);
#pragma unroll
        for (int mt = 0; mt < 4; mt++) {
            int row = warpM * 64 + mt * 16 + (lane & 15);
            uint32_t off = row * 256 + ((ca ^ (row & 7)) << 4);
            uint32_t Ah[4], Al[4];
            ldsm_x4(sb + ah + off, Ah[0], Ah[1], Ah[2], Ah[3]);
            ldsm_x4(sb + al + off, Al[0], Al[1], Al[2], Al[3]);
#pragma unroll
            for (int nt = 0; nt < 4; nt++) {
                mma_bf16(acc[mt][nt], Ah, Bh[nt]);
                mma_bf16(acc[mt][nt], Al, Bh[nt]);
                mma_bf16(acc[mt][nt], Ah, Bl[nt]);
            }
        }
    }
}

#define T32K 32768u

/* ---------------- generic C = A@B (+bias) via HMMA, K=128 ---------------- */
__global__ void __launch_bounds__(256) lin_mma(const float* __restrict__ A,
        const float* __restrict__ B, const float* __restrict__ bias,
        float* __restrict__ C, int N)
{
    extern __shared__ char smc[];
    const uint32_t sb = smem_u32(smc);
    const int tid = threadIdx.x, wid = tid >> 5, lane = tid & 31;
    const int warpM = wid >> 2, warpN = wid & 3;
    const int m0 = blockIdx.x * 128, n0 = blockIdx.y * 128;

    load_split_rowk(smc, 0, T32K, A + (long)m0 * 128, 128, tid);
    load_split_coln(smc, 2 * T32K, 3 * T32K, B + n0, N, tid);
    __syncthreads();

    float acc[4][4][4] = {};
    mma_k128(sb, 0, T32K, 2 * T32K, 3 * T32K, acc, warpM, warpN, lane);

    const int gr = lane >> 2, idx = lane & 3;
#pragma unroll
    for (int mt = 0; mt < 4; mt++) {
        int r0 = m0 + warpM * 64 + mt * 16 + gr;
#pragma unroll
        for (int nt = 0; nt < 4; nt++) {
            int col = n0 + warpN * 32 + nt * 8 + 2 * idx;
            float b0 = bias ? bias[col] : 0.f;
            float b1 = bias ? bias[col + 1] : 0.f;
            *(float2*)&C[(long)r0 * N + col] =
                make_float2(acc[mt][nt][0] + b0, acc[mt][nt][1] + b1);
            *(float2*)&C[(long)(r0 + 8) * N + col] =
                make_float2(acc[mt][nt][2] + b0, acc[mt][nt][3] + b1);
        }
    }
}

/* ---------------- GI and GH in one z-batched launch (N=384) ---------------- */
__global__ void __launch_bounds__(256) lin2_mma(const float* __restrict__ A0,
        const float* __restrict__ A1, const float* __restrict__ B0,
        const float* __restrict__ B1, const float* __restrict__ bias0,
        float* __restrict__ C0, float* __restrict__ C1)
{
    extern __shared__ char smc[];
    const uint32_t sb = smem_u32(smc);
    const int tid = threadIdx.x, wid = tid >> 5, lane = tid & 31;
    const int warpM = wid >> 2, warpN = wid & 3;
    const int m0 = blockIdx.x * 128, n0 = blockIdx.y * 128;
    const int z = blockIdx.z;
    const float* A = z ? A1 : A0;
    const float* B = z ? B1 : B0;
    const float* bias = z ? nullptr : bias0;
    float* C = z ? C1 : C0;

    load_split_rowk(smc, 0, T32K, A + (long)m0 * 128, 128, tid);
    load_split_coln(smc, 2 * T32K, 3 * T32K, B + n0, 384, tid);
    __syncthreads();

    float acc[4][4][4] = {};
    mma_k128(sb, 0, T32K, 2 * T32K, 3 * T32K, acc, warpM, warpN, lane);

    const int gr = lane >> 2, idx = lane & 3;
#pragma unroll
    for (int mt = 0; mt < 4; mt++) {
        int r0 = m0 + warpM * 64 + mt * 16 + gr;
#pragma unroll
        for (int nt = 0; nt < 4; nt++) {
            int col = n0 + warpN * 32 + nt * 8 + 2 * idx;
            float b0 = bias ? bias[col] : 0.f;
            float b1 = bias ? bias[col + 1] : 0.f;
            *(float2*)&C[(long)r0 * 384 + col] =
                make_float2(acc[mt][nt][0] + b0, acc[mt][nt][1] + b1);
            *(float2*)&C[(long)(r0 + 8) * 384 + col] =
                make_float2(acc[mt][nt][2] + b0, acc[mt][nt][3] + b1);
        }
    }
}

/* ---------------- per-edge transform, transposed-split output ---------------- */
__global__ void __launch_bounds__(256) pe_mma(const float* __restrict__ h,
                                              const float* __restrict__ Wmsg)
{
    extern __shared__ char smc[];
    const uint32_t sb = smem_u32(smc);
    const int tid = threadIdx.x, wid = tid >> 5, lane = tid & 31;
    const int warpM = wid >> 2, warpN = wid & 3;
    const int s0 = blockIdx.x * 128, e = blockIdx.y;

    load_split_rowk(smc, 0, T32K, h + (long)s0 * 128, 128, tid);
    load_split_coln(smc, 2 * T32K, 3 * T32K, Wmsg + (long)e * 16384, 128, tid);
    __syncthreads();

    float acc[4][4][4] = {};
    mma_k128(sb, 0, T32K, 2 * T32K, 3 * T32K, acc, warpM, warpN, lane);

    __syncthreads();
    float* tb = (float*)smc;                      /* [128 d][132] */
    const int gr = lane >> 2, idx = lane & 3;
#pragma unroll
    for (int mt = 0; mt < 4; mt++) {
        int sr = warpM * 64 + mt * 16 + gr;
#pragma unroll
        for (int nt = 0; nt < 4; nt++) {
            int d = warpN * 32 + nt * 8 + 2 * idx;
            tb[d * 132 + sr]           = acc[mt][nt][0];
            tb[(d + 1) * 132 + sr]     = acc[mt][nt][1];
            tb[d * 132 + sr + 8]       = acc[mt][nt][2];
            tb[(d + 1) * 132 + sr + 8] = acc[mt][nt][3];
        }
    }
    __syncthreads();
#pragma unroll
    for (int i = 0; i < 16; i++) {
        int lin = i * 256 + tid;
        int d = lin >> 5, c4 = lin & 31;
        int s = c4 * 4;
        float4 v = *(const float4*)&tb[d * 132 + s];
        __align__(8) __nv_bfloat16 hb[4], lb[4];
        split4(v, hb, lb);
        long o = (long)d * K_BIG + (long)e * 2048 + s0 + s;
        *(uint2*)&g_Pt_hi[o] = *(const uint2*)hb;
        *(uint2*)&g_Pt_lo[o] = *(const uint2*)lb;
    }
}

/* ---------------- readout NT ---------------- */
__global__ void __launch_bounds__(256) nt_mma(const float* __restrict__ hA,
        const float* __restrict__ h, float* __restrict__ C)
{
    extern __shared__ char smc[];
    const uint32_t sb = smem_u32(smc);
    const int tid = threadIdx.x, wid = tid >> 5, lane = tid & 31;
    const int warpM = wid >> 2, warpN = wid & 3;
    const int i0 = blockIdx.x * 128, j0 = blockIdx.y * 128;

    load_split_rowk(smc, 0, T32K, hA + (long)i0 * 128, 128, tid);
    load_split_rowk(smc, 2 * T32K, 3 * T32K, h + (long)j0 * 128, 128, tid);
    __syncthreads();

    float acc[4][4][4] = {};
    mma_k128(sb, 0, T32K, 2 * T32K, 3 * T32K, acc, warpM, warpN, lane);

    const int gr = lane >> 2, idx = lane & 3;
#pragma unroll
    for (int mt = 0; mt < 4; mt++) {
        int r0 = i0 + warpM * 64 + mt * 16 + gr;
#pragma unroll
        for (int nt = 0; nt < 4; nt++) {
            int col = j0 + warpN * 32 + nt * 8 + 2 * idx;
            *(float2*)&C[(long)r0 * N_NODES + col] = make_float2(acc[mt][nt][0], acc[mt][nt][1]);
            *(float2*)&C[(long)(r0 + 8) * N_NODES + col] = make_float2(acc[mt][nt][2], acc[mt][nt][3]);
        }
    }
}

/* =============== one-time edge transpose+split (coalesced writes) =============== */
__global__ void edge_split_kernel(const float* __restrict__ edge)
{
    __shared__ float sm[64][133];
    const int s0 = blockIdx.x * 64, t0 = blockIdx.y * 16;
    const int tid = threadIdx.x;
#pragma unroll
    for (int it = 0; it < 8; it++) {
        int lin = it * 256 + tid;          /* 2048 float4s */
        int s_l = lin >> 5, f4 = lin & 31;
        float4 v = *(const float4*)&edge[(long)(s0 + s_l) * K_BIG + t0 * 8 + f4 * 4];
        sm[s_l][f4 * 4 + 0] = v.x; sm[s_l][f4 * 4 + 1] = v.y;
        sm[s_l][f4 * 4 + 2] = v.z; sm[s_l][f4 * 4 + 3] = v.w;
    }
    __syncthreads();
    /* each thread: 8 consecutive s for one (t,e) -> 16B contiguous store */
#pragma unroll
    for (int it = 0; it < 4; it++) {
        int lin = it * 256 + tid;          /* 0..1023 */
        int sc  = lin & 7;                 /* s chunk  */
        int e   = (lin >> 3) & 7;
        int t_l = lin >> 6;                /* 0..15 */
        __align__(16) __nv_bfloat16 hb[8], lb[8];
#pragma unroll
        for (int j = 0; j < 8; j++) {
            float f = sm[sc * 8 + j][t_l * 8 + e];
            __nv_bfloat16 h = __float2bfloat16(f);
            hb[j] = h;
            lb[j] = __float2bfloat16(f - __bfloat162float(h));
        }
        long o = (long)(t0 + t_l) * K_BIG + (long)e * 2048 + s0 + sc * 8;
        *(uint4*)&g_edgeK_hi[o] = *(const uint4*)hb;
        *(uint4*)&g_edgeK_lo[o] = *(const uint4*)lb;
    }
}

/* =============== big message GEMM (pipelined HMMA) =============== */
#define MTILE_B 8192u
#define MSTAGE_B 32768u

__global__ void __launch_bounds__(256, 2) msg_mma_kernel()
{
    extern __shared__ char smc[];
    const uint32_t sb = smem_u32(smc);
    const int tid = threadIdx.x;
    const int wid = tid >> 5, lane = tid & 31;
    const int warpM = wid >> 2, warpN = wid & 3;
    const int t0 = blockIdx.x * 128;
    const int e = blockIdx.y, sh = blockIdx.z;
    const long koff = (long)e * 2048 + sh * 1024;

    const __nv_bfloat16* __restrict__ bAh = g_edgeK_hi + (long)t0 * K_BIG + koff;
    const __nv_bfloat16* __restrict__ bAl = g_edgeK_lo + (long)t0 * K_BIG + koff;
    const __nv_bfloat16* __restrict__ bBh = g_Pt_hi + koff;
    const __nv_bfloat16* __restrict__ bBl = g_Pt_lo + koff;

    float acc[4][4][4] = {};

    auto issue = [&](int chunk, int st) {
        const int kofs = chunk * 32;
        const __nv_bfloat16* srcs[4] = { bAh + kofs, bAl + kofs, bBh + kofs, bBl + kofs };
        const uint32_t stage = sb + st * MSTAGE_B;
#pragma unroll
        for (int j = 0; j < 4; j++) {
#pragma unroll
            for (int it = 0; it < 2; it++) {
                int seg = it * 256 + tid;
                int row = seg >> 2, c = seg & 3;
                uint32_t saddr = stage + j * MTILE_B + row * 64 +
                                 ((c ^ ((row >> 1) & 3)) << 4);
                cp_async16(saddr, srcs[j] + (long)row * K_BIG + c * 8);
            }
        }
    };

    issue(0, 0); CP_COMMIT();
    issue(1, 1); CP_COMMIT();
    issue(2, 2); CP_COMMIT();

    for (int chunk = 0; chunk < 32; chunk++) {
        CP_WAIT2();
        __syncthreads();
        const uint32_t stage = sb + (chunk % 3) * MSTAGE_B;

#pragma unroll
        for (int ks = 0; ks < 2; ks++) {
            uint32_t Bh[4][2], Bl[4][2];
            const int cb = ks * 2 + ((lane >> 3) & 1);
#pragma unroll
            for (int nt = 0; nt < 4; nt++) {
                int row = warpN * 32 + nt * 8 + (lane & 7);
                uint32_t off = row * 64 + ((cb ^ ((row >> 1) & 3)) << 4);
                ldsm_x2(stage + 2 * MTILE_B + off, Bh[nt][0], Bh[nt][1]);
                ldsm_x2(stage + 3 * MTILE_B + off, Bl[nt][0], Bl[nt][1]);
            }
            const int ca = ks * 2 + (lane >> 4);
#pragma unroll
            for (int mt = 0; mt < 4; mt++) {
                int row = warpM * 64 + mt * 16 + (lane & 15);
                uint32_t off = row * 64 + ((ca ^ ((row >> 1) & 3)) << 4);
                uint32_t Ah[4], Al[4];
                ldsm_x4(stage + off, Ah[0], Ah[1], Ah[2], Ah[3]);
                ldsm_x4(stage + MTILE_B + off, Al[0], Al[1], Al[2], Al[3]);
#pragma unroll
                for (int nt = 0; nt < 4; nt++) {
                    mma_bf16(acc[mt][nt], Ah, Bh[nt]);
                    mma_bf16(acc[mt][nt], Al, Bh[nt]);
                    mma_bf16(acc[mt][nt], Ah, Bl[nt]);
                }
            }
        }
        __syncthreads();
        if (chunk + 3 < 32) issue(chunk + 3, chunk % 3);
        CP_COMMIT();
    }

    /* epilogue: bf16-split partials (halves partial traffic) */
    const int gr = lane >> 2, idx = lane & 3;
    const long pbase = (long)(e + 8 * sh) * N_NODES * D_DIM;
#pragma unroll
    for (int mt = 0; mt < 4; mt++) {
        int r0 = t0 + warpM * 64 + mt * 16 + gr;
#pragma unroll
        for (int nt = 0; nt < 4; nt++) {
            int col = warpN * 32 + nt * 8 + 2 * idx;
            store_split2(g_part_hi, g_part_lo, pbase + (long)r0 * D_DIM + col,
                         acc[mt][nt][0], acc[mt][nt][1]);
            store_split2(g_part_hi, g_part_lo, pbase + (long)(r0 + 8) * D_DIM + col,
                         acc[mt][nt][2], acc[mt][nt][3]);
        }
    }
}

/* ---------------- reduce 16 bf16-split partials + bias ---------------- */
__global__ void reduce_bias(const float* __restrict__ bias)
{
    long idx = ((long)blockIdx.x * 256 + threadIdx.x) * 2;   /* < 262144 */
    float sx = bias[idx & 127], sy = bias[(idx + 1) & 127];
#pragma unroll
    for (int p = 0; p < 16; p++) {
        __nv_bfloat162 h = *(const __nv_bfloat162*)&g_part_hi[(long)p * 262144 + idx];
        __nv_bfloat162 l = *(const __nv_bfloat162*)&g_part_lo[(long)p * 262144 + idx];
        sx += __bfloat162float(h.x) + __bfloat162float(l.x);
        sy += __bfloat162float(h.y) + __bfloat162float(l.y);
    }
    *(float2*)&g_scratch[OFF_MSG + idx] = make_float2(sx, sy);
}

/* ---------------- GRU elementwise update ---------------- */
__global__ void gru_kernel(int cur)
{
    int idx = blockIdx.x * 256 + threadIdx.x;
    int i = idx >> 7, d = idx & 127;
    const float* __restrict__ gi = g_scratch + OFF_GI;
    const float* __restrict__ gh = g_scratch + OFF_GH;
    const float* __restrict__ h  = g_scratch + (cur ? OFF_H1 : OFF_H0);
    float* __restrict__ ho = g_scratch + (cur ? OFF_H0 : OFF_H1);

    long base = (long)i * 384 + d;
    float ir = gi[base], iz = gi[base + 128], inn = gi[base + 256];
    float hr = gh[base], hz = gh[base + 128], hn  = gh[base + 256];
    float hv = h[idx];
    float r = 1.f / (1.f + expf(-(ir + hr)));
    float z = 1.f / (1.f + expf(-(iz + hz)));
    float n = tanhf(inn + r * hn);
    ho[idx] = (1.f - z) * n + z * hv;
}

/* ---------------- launcher ---------------- */
extern "C" void kernel_launch(void* const* d_in, const int* in_sizes, int n_in,
                              void* d_out, int out_size)
{
    const float* node = (const float*)d_in[0];
    const float* edge = (const float*)d_in[1];
    const float* Wmsg = (const float*)d_in[2];
    const float* bmsg = (const float*)d_in[3];
    const float* Wi   = (const float*)d_in[4];
    const float* Wh   = (const float*)d_in[5];
    const float* bgru = (const float*)d_in[6];
    const float* Aro  = (const float*)d_in[7];
    float* out = (float*)d_out;

    float* scratch = nullptr;
    cudaGetSymbolAddress((void**)&scratch, g_scratch);
    float* H0  = scratch + OFF_H0;
    float* H1  = scratch + OFF_H1;
    float* MSG = scratch + OFF_MSG;
    float* GI  = scratch + OFF_GI;
    float* GH  = scratch + OFF_GH;
    float* HA  = scratch + OFF_HA;

    cudaFuncSetAttribute(msg_mma_kernel, cudaFuncAttributeMaxDynamicSharedMemorySize, 3 * MSTAGE_B);
    cudaFuncSetAttribute(lin_mma, cudaFuncAttributeMaxDynamicSharedMemorySize, 131072);
    cudaFuncSetAttribute(lin2_mma, cudaFuncAttributeMaxDynamicSharedMemorySize, 131072);
    cudaFuncSetAttribute(pe_mma, cudaFuncAttributeMaxDynamicSharedMemorySize, 131072);
    cudaFuncSetAttribute(nt_mma, cudaFuncAttributeMaxDynamicSharedMemorySize, 131072);

    cudaMemcpyAsync(H0, node, (size_t)N_NODES * D_DIM * sizeof(float),
                    cudaMemcpyDeviceToDevice);

    edge_split_kernel<<<dim3(32, 128), 256>>>(edge);

    int cur = 0;
    for (int it = 0; it < GITERS; it++) {
        float* Hc = cur ? H1 : H0;
        pe_mma<<<dim3(16, 8), 256, 131072>>>(Hc, Wmsg);
        msg_mma_kernel<<<dim3(16, 8, 2), 256, 3 * MSTAGE_B>>>();
        reduce_bias<<<512, 256>>>(bmsg);
        lin2_mma<<<dim3(16, 3, 2), 256, 131072>>>(MSG, Hc, Wi, Wh, bgru, GI, GH);
        gru_kernel<<<1024, 256>>>(cur);
        cur ^= 1;
    }
    float* Hf = cur ? H1 : H0;
    lin_mma<<<dim3(16, 1), 256, 131072>>>(Hf, Aro, nullptr, HA, 128);
    nt_mma<<<dim3(16, 16), 256, 131072>>>(HA, Hf, out);
}